// round 1
// baseline (speedup 1.0000x reference)
#include <cuda_runtime.h>
#include <cstddef>

#define S_LEN 2048
#define DIM   2048
#define HEADS 16
#define HD    128
#define BATCH 4

// Scratch (allocation-free rule: __device__ globals)
__device__ float g_qkv[(size_t)BATCH * S_LEN * 3 * DIM];   // [B*S, 3*DIM]
__device__ float g_attn[(size_t)BATCH * S_LEN * DIM];      // [B*S, DIM]

// ---------------------------------------------------------------------------
// SGEMM: C[M,N] = A[M,K] @ B[K,N] + bias[N]
// 128x128 block tile, BK=16, 256 threads, 8x8 per-thread microtile.
// ---------------------------------------------------------------------------
__global__ __launch_bounds__(256) void sgemm_bias_kernel(
    const float* __restrict__ A, const float* __restrict__ B,
    const float* __restrict__ bias, float* __restrict__ C,
    int M, int N, int K)
{
    __shared__ float As[16][128];   // transposed: As[k][m]
    __shared__ float Bs[16][128];   // Bs[k][n]

    const int tid = threadIdx.x;
    const int m0 = blockIdx.y * 128;
    const int n0 = blockIdx.x * 128;
    const int tx = tid & 15;        // col group
    const int ty = tid >> 4;        // row group

    float acc[8][8];
#pragma unroll
    for (int i = 0; i < 8; i++)
#pragma unroll
        for (int j = 0; j < 8; j++) acc[i][j] = 0.f;

    const int arow = tid >> 2;           // 0..63 (+64)
    const int acol = (tid & 3) * 4;      // 0,4,8,12
    const int brow = tid >> 5;           // 0..7 (+8)
    const int bcol = (tid & 31) * 4;     // 0..124

    const float* Ag = A + (size_t)m0 * K;
    const float* Bg = B + n0;

    for (int k0 = 0; k0 < K; k0 += 16) {
        float4 a0 = *(const float4*)(Ag + (size_t)arow * K + k0 + acol);
        float4 a1 = *(const float4*)(Ag + (size_t)(arow + 64) * K + k0 + acol);
        float4 b0 = *(const float4*)(Bg + (size_t)(k0 + brow) * N + bcol);
        float4 b1 = *(const float4*)(Bg + (size_t)(k0 + brow + 8) * N + bcol);

        __syncthreads();
        As[acol + 0][arow] = a0.x;
        As[acol + 1][arow] = a0.y;
        As[acol + 2][arow] = a0.z;
        As[acol + 3][arow] = a0.w;
        As[acol + 0][arow + 64] = a1.x;
        As[acol + 1][arow + 64] = a1.y;
        As[acol + 2][arow + 64] = a1.z;
        As[acol + 3][arow + 64] = a1.w;
        *(float4*)&Bs[brow][bcol] = b0;
        *(float4*)&Bs[brow + 8][bcol] = b1;
        __syncthreads();

#pragma unroll
        for (int k = 0; k < 16; k++) {
            float av[8], bv[8];
            *(float4*)&av[0] = *(float4*)&As[k][ty * 8];
            *(float4*)&av[4] = *(float4*)&As[k][ty * 8 + 4];
            *(float4*)&bv[0] = *(float4*)&Bs[k][tx * 8];
            *(float4*)&bv[4] = *(float4*)&Bs[k][tx * 8 + 4];
#pragma unroll
            for (int i = 0; i < 8; i++)
#pragma unroll
                for (int j = 0; j < 8; j++)
                    acc[i][j] += av[i] * bv[j];
        }
    }

    // epilogue: add bias, store
#pragma unroll
    for (int i = 0; i < 8; i++) {
        size_t row = (size_t)(m0 + ty * 8 + i);
#pragma unroll
        for (int j4 = 0; j4 < 2; j4++) {
            int col = n0 + tx * 8 + j4 * 4;
            float4 bsv = *(const float4*)(bias + col);
            float4 w;
            w.x = acc[i][j4 * 4 + 0] + bsv.x;
            w.y = acc[i][j4 * 4 + 1] + bsv.y;
            w.z = acc[i][j4 * 4 + 2] + bsv.z;
            w.w = acc[i][j4 * 4 + 3] + bsv.w;
            *(float4*)(C + row * N + col) = w;
        }
    }
}

// ---------------------------------------------------------------------------
// Flash attention with segment + causal mask.
// grid (S/64, HEADS, BATCH), 256 threads. Q tile = 64 rows, KV tiles = 64.
// ---------------------------------------------------------------------------
#define QS_STRIDE 132
#define KT_STRIDE 68
#define SS_STRIDE 68
// floats: Qs 64*132=8448, Kt 128*68=8704, Vs 64*132=8448, Ss 64*68=4352,
// row_m/l/scale 3*64, qid/kid 2*64 ints
#define ATTN_SMEM_BYTES ((8448 + 8704 + 8448 + 4352 + 192) * 4 + 128 * 4)

__global__ __launch_bounds__(256) void attn_kernel(
    const int* __restrict__ ids, float* __restrict__ out)
{
    extern __shared__ float sm[];
    float* Qs = sm;                       // [64][132]
    float* Kt = Qs + 64 * QS_STRIDE;      // [128][68]  (transposed)
    float* Vs = Kt + 128 * KT_STRIDE;     // [64][132]
    float* Ss = Vs + 64 * QS_STRIDE;      // [64][68]
    float* row_m = Ss + 64 * SS_STRIDE;
    float* row_l = row_m + 64;
    float* row_scale = row_l + 64;
    int* qid = (int*)(row_scale + 64);
    int* kid = qid + 64;

    const int b = blockIdx.z;
    const int h = blockIdx.y;
    const int q0 = blockIdx.x * 64;
    const int tid = threadIdx.x;
    const float scale = 0.08838834764831845f;   // 1/sqrt(128)

    const size_t base = (size_t)b * S_LEN * (3 * DIM);

    // load Q (scaled) + q ids
    for (int i = tid; i < 64 * 128; i += 256) {
        int tok = i >> 7, d = i & 127;
        Qs[tok * QS_STRIDE + d] =
            g_qkv[base + (size_t)(q0 + tok) * (3 * DIM) + h * HD + d] * scale;
    }
    if (tid < 64) {
        qid[tid] = ids[b * S_LEN + q0 + tid];
        row_m[tid] = -1e30f;
        row_l[tid] = 0.f;
    }

    // phase-1 mapping (S = Q K^T): rows ty*4..+3, cols tx*4..+3
    const int tx = tid & 15;
    const int ty = tid >> 4;
    // phase-3 mapping (O accumulate): rows rg*4..+3, cols cg*8..+7
    const int rg = tid >> 4;
    const int cg = tid & 15;
    const int pr0 = rg * 4;
    const int pc0 = cg * 8;

    float O[4][8];
#pragma unroll
    for (int i = 0; i < 4; i++)
#pragma unroll
        for (int j = 0; j < 8; j++) O[i][j] = 0.f;

    const int nkb = blockIdx.x;   // inclusive upper bound (causal)
    for (int kb = 0; kb <= nkb; kb++) {
        const int k0 = kb * 64;
        __syncthreads();   // protect Kt/Vs/Ss/kid from previous iteration readers

        for (int i = tid; i < 64 * 128; i += 256) {
            int tok = i >> 7, d = i & 127;
            size_t rowb = base + (size_t)(k0 + tok) * (3 * DIM) + h * HD + d;
            Kt[d * KT_STRIDE + tok] = g_qkv[rowb + DIM];
            Vs[tok * QS_STRIDE + d] = g_qkv[rowb + 2 * DIM];
        }
        if (tid < 64) kid[tid] = ids[b * S_LEN + k0 + tid];
        __syncthreads();

        // ---- phase 1: S tile (64x64) ----
        float acc[4][4];
#pragma unroll
        for (int i = 0; i < 4; i++)
#pragma unroll
            for (int j = 0; j < 4; j++) acc[i][j] = 0.f;

        for (int d = 0; d < 128; d++) {
            float qv[4], kv[4];
#pragma unroll
            for (int i = 0; i < 4; i++) qv[i] = Qs[(ty * 4 + i) * QS_STRIDE + d];
#pragma unroll
            for (int j = 0; j < 4; j++) kv[j] = Kt[d * KT_STRIDE + tx * 4 + j];
#pragma unroll
            for (int i = 0; i < 4; i++)
#pragma unroll
                for (int j = 0; j < 4; j++)
                    acc[i][j] += qv[i] * kv[j];
        }
#pragma unroll
        for (int i = 0; i < 4; i++) {
            int r = ty * 4 + i;
            int qi = q0 + r;
            int qidv = qid[r];
#pragma unroll
            for (int j = 0; j < 4; j++) {
                int c = tx * 4 + j;
                int kj = k0 + c;
                bool masked = (kj > qi) || (qidv != kid[c]);
                Ss[r * SS_STRIDE + c] = masked ? -1e30f : acc[i][j];
            }
        }
        __syncthreads();

        // ---- phase 2: online softmax (4 threads per row) ----
        {
            int r = tid >> 2;
            int qd = tid & 3;
            float* srow = Ss + r * SS_STRIDE + qd * 16;
            float mx = -1e30f;
#pragma unroll
            for (int c = 0; c < 16; c++) mx = fmaxf(mx, srow[c]);
            mx = fmaxf(mx, __shfl_xor_sync(0xffffffffu, mx, 1));
            mx = fmaxf(mx, __shfl_xor_sync(0xffffffffu, mx, 2));
            float m_old = row_m[r];
            float m_new = fmaxf(m_old, mx);
            float fac = __expf(m_old - m_new);
            float psum = 0.f;
#pragma unroll
            for (int c = 0; c < 16; c++) {
                float s = srow[c];
                float p = (s < -1e29f) ? 0.f : __expf(s - m_new);
                srow[c] = p;
                psum += p;
            }
            psum += __shfl_xor_sync(0xffffffffu, psum, 1);
            psum += __shfl_xor_sync(0xffffffffu, psum, 2);
            if (qd == 0) {
                row_m[r] = m_new;
                row_l[r] = row_l[r] * fac + psum;
                row_scale[r] = fac;
            }
        }
        __syncthreads();

        // ---- phase 3: rescale O, accumulate P @ V ----
        float fr[4];
#pragma unroll
        for (int i = 0; i < 4; i++) fr[i] = row_scale[pr0 + i];
#pragma unroll
        for (int i = 0; i < 4; i++)
#pragma unroll
            for (int j = 0; j < 8; j++) O[i][j] *= fr[i];

        for (int jj = 0; jj < 64; jj++) {
            float p[4];
#pragma unroll
            for (int i = 0; i < 4; i++) p[i] = Ss[(pr0 + i) * SS_STRIDE + jj];
            float4 v0 = *(float4*)&Vs[jj * QS_STRIDE + pc0];
            float4 v1 = *(float4*)&Vs[jj * QS_STRIDE + pc0 + 4];
#pragma unroll
            for (int i = 0; i < 4; i++) {
                O[i][0] += p[i] * v0.x;
                O[i][1] += p[i] * v0.y;
                O[i][2] += p[i] * v0.z;
                O[i][3] += p[i] * v0.w;
                O[i][4] += p[i] * v1.x;
                O[i][5] += p[i] * v1.y;
                O[i][6] += p[i] * v1.z;
                O[i][7] += p[i] * v1.w;
            }
        }
    }

    // ---- epilogue: normalize and write [b, s, h*HD + d] ----
#pragma unroll
    for (int i = 0; i < 4; i++) {
        float inv = 1.f / row_l[pr0 + i];
        size_t orow = ((size_t)b * S_LEN + q0 + pr0 + i) * DIM + h * HD + pc0;
        float4 w0, w1;
        w0.x = O[i][0] * inv; w0.y = O[i][1] * inv;
        w0.z = O[i][2] * inv; w0.w = O[i][3] * inv;
        w1.x = O[i][4] * inv; w1.y = O[i][5] * inv;
        w1.z = O[i][6] * inv; w1.w = O[i][7] * inv;
        *(float4*)(out + orow) = w0;
        *(float4*)(out + orow + 4) = w1;
    }
}

// ---------------------------------------------------------------------------
extern "C" void kernel_launch(void* const* d_in, const int* in_sizes, int n_in,
                              void* d_out, int out_size)
{
    const float* x    = (const float*)d_in[0];   // [4,2048,2048]
    const int*   ids  = (const int*)d_in[1];     // [4,2048]
    const float* Wqkv = (const float*)d_in[2];   // [2048,6144]
    const float* bqkv = (const float*)d_in[3];   // [6144]
    const float* Wo   = (const float*)d_in[4];   // [2048,2048]
    const float* bo   = (const float*)d_in[5];   // [2048]
    float* out = (float*)d_out;

    float* qkv_ptr = nullptr;
    float* attn_ptr = nullptr;
    cudaGetSymbolAddress((void**)&qkv_ptr, g_qkv);
    cudaGetSymbolAddress((void**)&attn_ptr, g_attn);

    cudaFuncSetAttribute(attn_kernel,
                         cudaFuncAttributeMaxDynamicSharedMemorySize,
                         ATTN_SMEM_BYTES);

    const int M = BATCH * S_LEN;   // 8192

    // 1) QKV = x @ Wqkv + bqkv      [8192, 6144]
    {
        dim3 grid(3 * DIM / 128, M / 128);
        sgemm_bias_kernel<<<grid, 256>>>(x, Wqkv, bqkv, qkv_ptr, M, 3 * DIM, DIM);
    }
    // 2) attention -> g_attn        [8192, 2048]
    {
        dim3 grid(S_LEN / 64, HEADS, BATCH);
        attn_kernel<<<grid, 256, ATTN_SMEM_BYTES>>>(ids, attn_ptr);
    }
    // 3) out = attn @ Wo + bo       [8192, 2048]
    {
        dim3 grid(DIM / 128, M / 128);
        sgemm_bias_kernel<<<grid, 256>>>(attn_ptr, Wo, bo, out, M, DIM, DIM);
    }
}

// round 3
// speedup vs baseline: 1.6130x; 1.6130x over previous
#include <cuda_runtime.h>
#include <cstdint>
#include <cstddef>

#define S_LEN 2048
#define DIM   2048
#define HEADS 16
#define HD    128
#define BATCH 4

// Scratch (allocation-free rule: __device__ globals)
__device__ float g_qkv[(size_t)BATCH * S_LEN * 3 * DIM];   // [B*S, 3*DIM]
__device__ float g_attn[(size_t)BATCH * S_LEN * DIM];      // [B*S, DIM]
__device__ float g_wqkvT[(size_t)(3 * DIM) * DIM];         // [6144, 2048]
__device__ float g_woT[(size_t)DIM * DIM];                 // [2048, 2048]

// ---------------------------------------------------------------------------
// helpers
// ---------------------------------------------------------------------------
__device__ __forceinline__ uint32_t smem_to_u32(const void* p) {
    uint32_t a;
    asm("{ .reg .u64 t; cvta.to.shared.u64 t, %1; cvt.u32.u64 %0, t; }"
        : "=r"(a) : "l"(p));
    return a;
}

__device__ __forceinline__ void ldsm4(uint32_t* r, uint32_t addr) {
    asm volatile("ldmatrix.sync.aligned.m8n8.x4.shared.b16 {%0,%1,%2,%3}, [%4];"
                 : "=r"(r[0]), "=r"(r[1]), "=r"(r[2]), "=r"(r[3]) : "r"(addr));
}

__device__ __forceinline__ void mma_bf16(float* d, const uint32_t* a, const uint32_t* b) {
    asm volatile(
        "mma.sync.aligned.m16n8k16.row.col.f32.bf16.bf16.f32 "
        "{%0,%1,%2,%3}, {%4,%5,%6,%7}, {%8,%9}, {%0,%1,%2,%3};"
        : "+f"(d[0]), "+f"(d[1]), "+f"(d[2]), "+f"(d[3])
        : "r"(a[0]), "r"(a[1]), "r"(a[2]), "r"(a[3]), "r"(b[0]), "r"(b[1]));
}

// pack (x0,x1) -> bf16x2 hi (low half = x0) and bf16x2 lo (residuals)
__device__ __forceinline__ void split_bf16x2(float x0, float x1,
                                             uint32_t& hi, uint32_t& lo) {
    asm("cvt.rn.bf16x2.f32 %0, %1, %2;" : "=r"(hi) : "f"(x1), "f"(x0));
    float h0 = __uint_as_float(hi << 16);
    float h1 = __uint_as_float(hi & 0xffff0000u);
    float r0 = x0 - h0;
    float r1 = x1 - h1;
    asm("cvt.rn.bf16x2.f32 %0, %1, %2;" : "=r"(lo) : "f"(r1), "f"(r0));
}

#define STS64U(addr, a, b) \
    asm volatile("st.shared.v2.b32 [%0], {%1, %2};" \
                 :: "r"(addr), "r"(a), "r"(b) : "memory")

// ---------------------------------------------------------------------------
// Transpose: in[R][C] -> out[C][R]
// ---------------------------------------------------------------------------
__global__ __launch_bounds__(256) void transpose_kernel(
    const float* __restrict__ in, float* __restrict__ out, int R, int C)
{
    __shared__ float t[32][33];
    int bx = blockIdx.x * 32;
    int by = blockIdx.y * 32;
    int x = threadIdx.x, y = threadIdx.y;   // 32 x 8
#pragma unroll
    for (int j = 0; j < 32; j += 8)
        t[y + j][x] = in[(size_t)(by + y + j) * C + bx + x];
    __syncthreads();
#pragma unroll
    for (int j = 0; j < 32; j += 8)
        out[(size_t)(bx + y + j) * R + by + x] = t[x][y + j];
}

// ---------------------------------------------------------------------------
// bf16 3-pass split GEMM on mma.sync: C[M,N] = A[M,K] @ Bt[N,K]^T + bias[N]
// CTA tile 128x128, BK=32, 256 threads (8 warps, warp tile 32x64),
// double-buffered smem, LDG prefetch 2 iters ahead.
//
// Smem per stage (bf16, row stride 80B = 40 elems, 32 k used):
//   Ahi [128][40] @ 0      Alo @ 10240
//   Bhi [128][40] @ 20480  Blo @ 30720      stage stride 40960
// ---------------------------------------------------------------------------
#define GSTRIDE      80          // bytes per smem row
#define GSTAGE_BYTES 40960
#define GSMEM_BYTES  (2 * GSTAGE_BYTES)

__global__ __launch_bounds__(256, 1) void gemm_bf16s_kernel(
    const float* __restrict__ A, const float* __restrict__ Bt,
    const float* __restrict__ bias, float* __restrict__ C,
    int M, int N, int K)
{
    extern __shared__ __align__(1024) char smem[];
    const uint32_t sb = smem_to_u32(smem);
    const int tid = threadIdx.x;
    const int wid = tid >> 5, lid = tid & 31;
    const int wm = wid >> 1;          // 0..3  (32-row slab)
    const int wn = wid & 1;           // 0..1  (64-col slab)
    const int m0 = blockIdx.y * 128;
    const int n0 = blockIdx.x * 128;

    // ldmatrix per-lane base offsets (bytes)
    const uint32_t aBase = (uint32_t)((wm * 32 + (lid & 15)) * GSTRIDE + (lid >> 4) * 16);
    const uint32_t bBase = (uint32_t)((wn * 64 + ((lid >> 1) & 8) + (lid & 7)) * GSTRIDE
                                      + ((lid & 8) << 1));

    // loader mapping: 4 float4 per thread per operand tile
    const int rr0 = tid >> 3;         // +32 per j
    const int c4  = tid & 7;          // k-quad

    float acc[2][8][4];
#pragma unroll
    for (int mf = 0; mf < 2; mf++)
#pragma unroll
        for (int nf = 0; nf < 8; nf++)
#pragma unroll
            for (int q = 0; q < 4; q++) acc[mf][nf][q] = 0.f;

    const int niter = K >> 5;

    float4 av[4], bv[4];

    auto ldg_tile = [&](int i) {
        const int k0 = i << 5;
#pragma unroll
        for (int j = 0; j < 4; j++) {
            int rr = rr0 + 32 * j;
            av[j] = *(const float4*)(A  + (size_t)(m0 + rr) * K + k0 + c4 * 4);
            bv[j] = *(const float4*)(Bt + (size_t)(n0 + rr) * K + k0 + c4 * 4);
        }
    };

    auto sts_tile = [&](int s) {
        const uint32_t base = sb + s * GSTAGE_BYTES;
#pragma unroll
        for (int j = 0; j < 4; j++) {
            int rr = rr0 + 32 * j;
            uint32_t off = (uint32_t)(rr * GSTRIDE + c4 * 8);
            uint32_t h0, l0, h1, l1;
            split_bf16x2(av[j].x, av[j].y, h0, l0);
            split_bf16x2(av[j].z, av[j].w, h1, l1);
            STS64U(base + off, h0, h1);
            STS64U(base + 10240 + off, l0, l1);
            split_bf16x2(bv[j].x, bv[j].y, h0, l0);
            split_bf16x2(bv[j].z, bv[j].w, h1, l1);
            STS64U(base + 20480 + off, h0, h1);
            STS64U(base + 30720 + off, l0, l1);
        }
    };

    // prologue
    ldg_tile(0);
    sts_tile(0);
    if (niter > 1) ldg_tile(1);
    __syncthreads();

    for (int i = 0; i < niter; i++) {
        const int s = i & 1;
        if (i + 1 < niter) sts_tile(s ^ 1);
        if (i + 2 < niter) ldg_tile(i + 2);

        const uint32_t sA = sb + s * GSTAGE_BYTES;
#pragma unroll
        for (int kstep = 0; kstep < 2; kstep++) {
            const uint32_t koff = kstep * 32;
            uint32_t ahi[2][4], alo[2][4];
            ldsm4(ahi[0], sA + aBase + koff);
            ldsm4(ahi[1], sA + aBase + 16 * GSTRIDE + koff);
            ldsm4(alo[0], sA + 10240 + aBase + koff);
            ldsm4(alo[1], sA + 10240 + aBase + 16 * GSTRIDE + koff);
            uint32_t bhi[8][2], blo[8][2];
#pragma unroll
            for (int t = 0; t < 4; t++) {
                uint32_t r[4];
                ldsm4(r, sA + 20480 + bBase + t * 16 * GSTRIDE + koff);
                bhi[2 * t][0] = r[0]; bhi[2 * t][1] = r[1];
                bhi[2 * t + 1][0] = r[2]; bhi[2 * t + 1][1] = r[3];
                ldsm4(r, sA + 30720 + bBase + t * 16 * GSTRIDE + koff);
                blo[2 * t][0] = r[0]; blo[2 * t][1] = r[1];
                blo[2 * t + 1][0] = r[2]; blo[2 * t + 1][1] = r[3];
            }
#pragma unroll
            for (int mf = 0; mf < 2; mf++)
#pragma unroll
                for (int nf = 0; nf < 8; nf++) {
                    mma_bf16(acc[mf][nf], ahi[mf], bhi[nf]);
                    mma_bf16(acc[mf][nf], ahi[mf], blo[nf]);
                    mma_bf16(acc[mf][nf], alo[mf], bhi[nf]);
                }
        }
        __syncthreads();
    }

    // epilogue
    const int erow = m0 + wm * 32 + (lid >> 2);
    const int ecol0 = n0 + wn * 64 + (lid & 3) * 2;
#pragma unroll
    for (int mf = 0; mf < 2; mf++) {
#pragma unroll
        for (int nf = 0; nf < 8; nf++) {
            int col = ecol0 + nf * 8;
            float2 bz = *(const float2*)(bias + col);
            float2 v0, v1;
            v0.x = acc[mf][nf][0] + bz.x; v0.y = acc[mf][nf][1] + bz.y;
            v1.x = acc[mf][nf][2] + bz.x; v1.y = acc[mf][nf][3] + bz.y;
            size_t r0 = (size_t)(erow + mf * 16) * N + col;
            *(float2*)(C + r0) = v0;
            *(float2*)(C + r0 + 8 * N) = v1;
        }
    }
}

// ---------------------------------------------------------------------------
// Flash attention with segment + causal mask (validated in R1).
// grid (S/64, HEADS, BATCH), 256 threads.
// ---------------------------------------------------------------------------
#define QS_STRIDE 132
#define KT_STRIDE 68
#define SS_STRIDE 68
#define ATTN_SMEM_BYTES ((8448 + 8704 + 8448 + 4352 + 192) * 4 + 128 * 4)

__global__ __launch_bounds__(256) void attn_kernel(
    const int* __restrict__ ids, float* __restrict__ out)
{
    extern __shared__ float sm[];
    float* Qs = sm;
    float* Kt = Qs + 64 * QS_STRIDE;
    float* Vs = Kt + 128 * KT_STRIDE;
    float* Ss = Vs + 64 * QS_STRIDE;
    float* row_m = Ss + 64 * SS_STRIDE;
    float* row_l = row_m + 64;
    float* row_scale = row_l + 64;
    int* qid = (int*)(row_scale + 64);
    int* kid = qid + 64;

    const int b = blockIdx.z;
    const int h = blockIdx.y;
    const int q0 = blockIdx.x * 64;
    const int tid = threadIdx.x;
    const float scale = 0.08838834764831845f;

    const size_t base = (size_t)b * S_LEN * (3 * DIM);

    for (int i = tid; i < 64 * 128; i += 256) {
        int tok = i >> 7, d = i & 127;
        Qs[tok * QS_STRIDE + d] =
            g_qkv[base + (size_t)(q0 + tok) * (3 * DIM) + h * HD + d] * scale;
    }
    if (tid < 64) {
        qid[tid] = ids[b * S_LEN + q0 + tid];
        row_m[tid] = -1e30f;
        row_l[tid] = 0.f;
    }

    const int tx = tid & 15;
    const int ty = tid >> 4;
    const int pr0 = (tid >> 4) * 4;
    const int pc0 = (tid & 15) * 8;

    float O[4][8];
#pragma unroll
    for (int i = 0; i < 4; i++)
#pragma unroll
        for (int j = 0; j < 8; j++) O[i][j] = 0.f;

    const int nkb = blockIdx.x;
    for (int kb = 0; kb <= nkb; kb++) {
        const int k0 = kb * 64;
        __syncthreads();

        for (int i = tid; i < 64 * 128; i += 256) {
            int tok = i >> 7, d = i & 127;
            size_t rowb = base + (size_t)(k0 + tok) * (3 * DIM) + h * HD + d;
            Kt[d * KT_STRIDE + tok] = g_qkv[rowb + DIM];
            Vs[tok * QS_STRIDE + d] = g_qkv[rowb + 2 * DIM];
        }
        if (tid < 64) kid[tid] = ids[b * S_LEN + k0 + tid];
        __syncthreads();

        float acc[4][4];
#pragma unroll
        for (int i = 0; i < 4; i++)
#pragma unroll
            for (int j = 0; j < 4; j++) acc[i][j] = 0.f;

        for (int d = 0; d < 128; d++) {
            float qv[4], kv[4];
#pragma unroll
            for (int i = 0; i < 4; i++) qv[i] = Qs[(ty * 4 + i) * QS_STRIDE + d];
#pragma unroll
            for (int j = 0; j < 4; j++) kv[j] = Kt[d * KT_STRIDE + tx * 4 + j];
#pragma unroll
            for (int i = 0; i < 4; i++)
#pragma unroll
                for (int j = 0; j < 4; j++)
                    acc[i][j] += qv[i] * kv[j];
        }
#pragma unroll
        for (int i = 0; i < 4; i++) {
            int r = ty * 4 + i;
            int qi = q0 + r;
            int qidv = qid[r];
#pragma unroll
            for (int j = 0; j < 4; j++) {
                int c = tx * 4 + j;
                int kj = k0 + c;
                bool masked = (kj > qi) || (qidv != kid[c]);
                Ss[r * SS_STRIDE + c] = masked ? -1e30f : acc[i][j];
            }
        }
        __syncthreads();

        {
            int r = tid >> 2;
            int qd = tid & 3;
            float* srow = Ss + r * SS_STRIDE + qd * 16;
            float mx = -1e30f;
#pragma unroll
            for (int c = 0; c < 16; c++) mx = fmaxf(mx, srow[c]);
            mx = fmaxf(mx, __shfl_xor_sync(0xffffffffu, mx, 1));
            mx = fmaxf(mx, __shfl_xor_sync(0xffffffffu, mx, 2));
            float m_old = row_m[r];
            float m_new = fmaxf(m_old, mx);
            float fac = __expf(m_old - m_new);
            float psum = 0.f;
#pragma unroll
            for (int c = 0; c < 16; c++) {
                float s = srow[c];
                float p = (s < -1e29f) ? 0.f : __expf(s - m_new);
                srow[c] = p;
                psum += p;
            }
            psum += __shfl_xor_sync(0xffffffffu, psum, 1);
            psum += __shfl_xor_sync(0xffffffffu, psum, 2);
            if (qd == 0) {
                row_m[r] = m_new;
                row_l[r] = row_l[r] * fac + psum;
                row_scale[r] = fac;
            }
        }
        __syncthreads();

        float fr[4];
#pragma unroll
        for (int i = 0; i < 4; i++) fr[i] = row_scale[pr0 + i];
#pragma unroll
        for (int i = 0; i < 4; i++)
#pragma unroll
            for (int j = 0; j < 8; j++) O[i][j] *= fr[i];

        for (int jj = 0; jj < 64; jj++) {
            float p[4];
#pragma unroll
            for (int i = 0; i < 4; i++) p[i] = Ss[(pr0 + i) * SS_STRIDE + jj];
            float4 v0 = *(float4*)&Vs[jj * QS_STRIDE + pc0];
            float4 v1 = *(float4*)&Vs[jj * QS_STRIDE + pc0 + 4];
#pragma unroll
            for (int i = 0; i < 4; i++) {
                O[i][0] += p[i] * v0.x;
                O[i][1] += p[i] * v0.y;
                O[i][2] += p[i] * v0.z;
                O[i][3] += p[i] * v0.w;
                O[i][4] += p[i] * v1.x;
                O[i][5] += p[i] * v1.y;
                O[i][6] += p[i] * v1.z;
                O[i][7] += p[i] * v1.w;
            }
        }
    }

#pragma unroll
    for (int i = 0; i < 4; i++) {
        float inv = 1.f / row_l[pr0 + i];
        size_t orow = ((size_t)b * S_LEN + q0 + pr0 + i) * DIM + h * HD + pc0;
        float4 w0, w1;
        w0.x = O[i][0] * inv; w0.y = O[i][1] * inv;
        w0.z = O[i][2] * inv; w0.w = O[i][3] * inv;
        w1.x = O[i][4] * inv; w1.y = O[i][5] * inv;
        w1.z = O[i][6] * inv; w1.w = O[i][7] * inv;
        *(float4*)(out + orow) = w0;
        *(float4*)(out + orow + 4) = w1;
    }
}

// ---------------------------------------------------------------------------
extern "C" void kernel_launch(void* const* d_in, const int* in_sizes, int n_in,
                              void* d_out, int out_size)
{
    const float* x    = (const float*)d_in[0];   // [4,2048,2048]
    const int*   ids  = (const int*)d_in[1];     // [4,2048]
    const float* Wqkv = (const float*)d_in[2];   // [2048,6144]
    const float* bqkv = (const float*)d_in[3];   // [6144]
    const float* Wo   = (const float*)d_in[4];   // [2048,2048]
    const float* bo   = (const float*)d_in[5];   // [2048]
    float* out = (float*)d_out;

    float *qkv_ptr, *attn_ptr, *wqkvT_ptr, *woT_ptr;
    cudaGetSymbolAddress((void**)&qkv_ptr, g_qkv);
    cudaGetSymbolAddress((void**)&attn_ptr, g_attn);
    cudaGetSymbolAddress((void**)&wqkvT_ptr, g_wqkvT);
    cudaGetSymbolAddress((void**)&woT_ptr, g_woT);

    cudaFuncSetAttribute(attn_kernel,
                         cudaFuncAttributeMaxDynamicSharedMemorySize,
                         ATTN_SMEM_BYTES);
    cudaFuncSetAttribute(gemm_bf16s_kernel,
                         cudaFuncAttributeMaxDynamicSharedMemorySize,
                         GSMEM_BYTES);

    const int M = BATCH * S_LEN;   // 8192

    // 0) transpose weights into K-major scratch
    {
        dim3 blk(32, 8);
        transpose_kernel<<<dim3(3 * DIM / 32, DIM / 32), blk>>>(Wqkv, wqkvT_ptr, DIM, 3 * DIM);
        transpose_kernel<<<dim3(DIM / 32, DIM / 32), blk>>>(Wo, woT_ptr, DIM, DIM);
    }
    // 1) QKV = x @ Wqkv + bqkv      [8192, 6144]
    {
        dim3 grid(3 * DIM / 128, M / 128);
        gemm_bf16s_kernel<<<grid, 256, GSMEM_BYTES>>>(x, wqkvT_ptr, bqkv, qkv_ptr, M, 3 * DIM, DIM);
    }
    // 2) attention -> g_attn        [8192, 2048]
    {
        dim3 grid(S_LEN / 64, HEADS, BATCH);
        attn_kernel<<<grid, 256, ATTN_SMEM_BYTES>>>(ids, attn_ptr);
    }
    // 3) out = attn @ Wo + bo       [8192, 2048]
    {
        dim3 grid(DIM / 128, M / 128);
        gemm_bf16s_kernel<<<grid, 256, GSMEM_BYTES>>>(attn_ptr, woT_ptr, bo, out, M, DIM, DIM);
    }
}

// round 4
// speedup vs baseline: 3.4639x; 2.1475x over previous
#include <cuda_runtime.h>
#include <cuda_bf16.h>
#include <cstdint>
#include <cstddef>

#define S_LEN 2048
#define DIM   2048
#define HEADS 16
#define HD    128
#define BATCH 4

// Scratch (allocation-free rule: __device__ globals)
__device__ float g_attn[(size_t)BATCH * S_LEN * DIM];      // [B*S, DIM]
__device__ float g_wqkvT[(size_t)(3 * DIM) * DIM];         // [6144, 2048]
__device__ float g_woT[(size_t)DIM * DIM];                 // [2048, 2048]
// bf16 hi/lo planes, layout [bh(64)][s(2048)][hd(128)]
#define PLANE_ELEMS ((size_t)BATCH * HEADS * S_LEN * HD)
__device__ __nv_bfloat16 g_qhi[PLANE_ELEMS], g_qlo[PLANE_ELEMS];
__device__ __nv_bfloat16 g_khi[PLANE_ELEMS], g_klo[PLANE_ELEMS];
__device__ __nv_bfloat16 g_vhi[PLANE_ELEMS], g_vlo[PLANE_ELEMS];

// ---------------------------------------------------------------------------
// helpers
// ---------------------------------------------------------------------------
__device__ __forceinline__ uint32_t smem_to_u32(const void* p) {
    uint32_t a;
    asm("{ .reg .u64 t; cvta.to.shared.u64 t, %1; cvt.u32.u64 %0, t; }"
        : "=r"(a) : "l"(p));
    return a;
}

__device__ __forceinline__ void ldsm4(uint32_t* r, uint32_t addr) {
    asm volatile("ldmatrix.sync.aligned.m8n8.x4.shared.b16 {%0,%1,%2,%3}, [%4];"
                 : "=r"(r[0]), "=r"(r[1]), "=r"(r[2]), "=r"(r[3]) : "r"(addr));
}

__device__ __forceinline__ void ldsm4t(uint32_t* r, uint32_t addr) {
    asm volatile("ldmatrix.sync.aligned.m8n8.x4.trans.shared.b16 {%0,%1,%2,%3}, [%4];"
                 : "=r"(r[0]), "=r"(r[1]), "=r"(r[2]), "=r"(r[3]) : "r"(addr));
}

__device__ __forceinline__ void mma_bf16(float* d, const uint32_t* a, const uint32_t* b) {
    asm volatile(
        "mma.sync.aligned.m16n8k16.row.col.f32.bf16.bf16.f32 "
        "{%0,%1,%2,%3}, {%4,%5,%6,%7}, {%8,%9}, {%0,%1,%2,%3};"
        : "+f"(d[0]), "+f"(d[1]), "+f"(d[2]), "+f"(d[3])
        : "r"(a[0]), "r"(a[1]), "r"(a[2]), "r"(a[3]), "r"(b[0]), "r"(b[1]));
}

// pack (x0,x1) -> bf16x2 hi (low half = x0) and bf16x2 lo (residuals)
__device__ __forceinline__ void split_bf16x2(float x0, float x1,
                                             uint32_t& hi, uint32_t& lo) {
    asm("cvt.rn.bf16x2.f32 %0, %1, %2;" : "=r"(hi) : "f"(x1), "f"(x0));
    float h0 = __uint_as_float(hi << 16);
    float h1 = __uint_as_float(hi & 0xffff0000u);
    float r0 = x0 - h0;
    float r1 = x1 - h1;
    asm("cvt.rn.bf16x2.f32 %0, %1, %2;" : "=r"(lo) : "f"(r1), "f"(r0));
}

#define STS64U(addr, a, b) \
    asm volatile("st.shared.v2.b32 [%0], {%1, %2};" \
                 :: "r"(addr), "r"(a), "r"(b) : "memory")

#define CP_ASYNC16(dst, src) \
    asm volatile("cp.async.cg.shared.global [%0], [%1], 16;" \
                 :: "r"(dst), "l"(src) : "memory")
#define CP_COMMIT() asm volatile("cp.async.commit_group;" ::: "memory")
#define CP_WAIT1()  asm volatile("cp.async.wait_group 1;" ::: "memory")

// ---------------------------------------------------------------------------
// Transpose: in[R][C] -> out[C][R]
// ---------------------------------------------------------------------------
__global__ __launch_bounds__(256) void transpose_kernel(
    const float* __restrict__ in, float* __restrict__ out, int R, int C)
{
    __shared__ float t[32][33];
    int bx = blockIdx.x * 32;
    int by = blockIdx.y * 32;
    int x = threadIdx.x, y = threadIdx.y;   // 32 x 8
#pragma unroll
    for (int j = 0; j < 32; j += 8)
        t[y + j][x] = in[(size_t)(by + y + j) * C + bx + x];
    __syncthreads();
#pragma unroll
    for (int j = 0; j < 32; j += 8)
        out[(size_t)(bx + y + j) * R + by + x] = t[x][y + j];
}

// ---------------------------------------------------------------------------
// Shared GEMM core defs (bf16 3-pass split, mma.sync, 128x128 tile, BK=32)
// ---------------------------------------------------------------------------
#define GSTRIDE      80
#define GSTAGE_BYTES 40960
#define GSMEM_BYTES  (2 * GSTAGE_BYTES)

// Core mainloop as a macro-expanded body shared by both GEMM kernels.
// Assumes declared: A, Bt, M(unused), N/K, m0, n0, tid, acc[2][8][4]
#define GEMM_CORE_BODY                                                        \
    extern __shared__ __align__(1024) char smem[];                            \
    const uint32_t sb = smem_to_u32(smem);                                    \
    const int tid = threadIdx.x;                                              \
    const int wid = tid >> 5, lid = tid & 31;                                 \
    const int wm = wid >> 1;                                                  \
    const int wn = wid & 1;                                                   \
    const int m0 = blockIdx.y * 128;                                          \
    const int n0 = blockIdx.x * 128;                                          \
    const uint32_t aBase = (uint32_t)((wm * 32 + (lid & 15)) * GSTRIDE + (lid >> 4) * 16); \
    const uint32_t bBase = (uint32_t)((wn * 64 + ((lid >> 1) & 8) + (lid & 7)) * GSTRIDE \
                                      + ((lid & 8) << 1));                    \
    const int rr0 = tid >> 3;                                                 \
    const int c4  = tid & 7;                                                  \
    float acc[2][8][4];                                                       \
    _Pragma("unroll")                                                         \
    for (int mf = 0; mf < 2; mf++)                                            \
        _Pragma("unroll")                                                     \
        for (int nf = 0; nf < 8; nf++)                                        \
            _Pragma("unroll")                                                 \
            for (int q = 0; q < 4; q++) acc[mf][nf][q] = 0.f;                 \
    const int niter = K >> 5;                                                 \
    float4 av[4], bv[4];                                                      \
    auto ldg_tile = [&](int i) {                                              \
        const int k0 = i << 5;                                                \
        _Pragma("unroll")                                                     \
        for (int j = 0; j < 4; j++) {                                         \
            int rr = rr0 + 32 * j;                                            \
            av[j] = *(const float4*)(A  + (size_t)(m0 + rr) * K + k0 + c4 * 4); \
            bv[j] = *(const float4*)(Bt + (size_t)(n0 + rr) * K + k0 + c4 * 4); \
        }                                                                     \
    };                                                                        \
    auto sts_tile = [&](int s) {                                              \
        const uint32_t base = sb + s * GSTAGE_BYTES;                          \
        _Pragma("unroll")                                                     \
        for (int j = 0; j < 4; j++) {                                         \
            int rr = rr0 + 32 * j;                                            \
            uint32_t off = (uint32_t)(rr * GSTRIDE + c4 * 8);                 \
            uint32_t h0, l0, h1, l1;                                          \
            split_bf16x2(av[j].x, av[j].y, h0, l0);                           \
            split_bf16x2(av[j].z, av[j].w, h1, l1);                           \
            STS64U(base + off, h0, h1);                                       \
            STS64U(base + 10240 + off, l0, l1);                               \
            split_bf16x2(bv[j].x, bv[j].y, h0, l0);                           \
            split_bf16x2(bv[j].z, bv[j].w, h1, l1);                           \
            STS64U(base + 20480 + off, h0, h1);                               \
            STS64U(base + 30720 + off, l0, l1);                               \
        }                                                                     \
    };                                                                        \
    ldg_tile(0);                                                              \
    sts_tile(0);                                                              \
    if (niter > 1) ldg_tile(1);                                               \
    __syncthreads();                                                          \
    for (int i = 0; i < niter; i++) {                                         \
        const int s = i & 1;                                                  \
        if (i + 1 < niter) sts_tile(s ^ 1);                                   \
        if (i + 2 < niter) ldg_tile(i + 2);                                   \
        const uint32_t sA = sb + s * GSTAGE_BYTES;                            \
        _Pragma("unroll")                                                     \
        for (int kstep = 0; kstep < 2; kstep++) {                             \
            const uint32_t koff = kstep * 32;                                 \
            uint32_t ahi[2][4], alo[2][4];                                    \
            ldsm4(ahi[0], sA + aBase + koff);                                 \
            ldsm4(ahi[1], sA + aBase + 16 * GSTRIDE + koff);                  \
            ldsm4(alo[0], sA + 10240 + aBase + koff);                         \
            ldsm4(alo[1], sA + 10240 + aBase + 16 * GSTRIDE + koff);          \
            uint32_t bhi[8][2], blo[8][2];                                    \
            _Pragma("unroll")                                                 \
            for (int t2 = 0; t2 < 4; t2++) {                                  \
                uint32_t r[4];                                                \
                ldsm4(r, sA + 20480 + bBase + t2 * 16 * GSTRIDE + koff);      \
                bhi[2 * t2][0] = r[0]; bhi[2 * t2][1] = r[1];                 \
                bhi[2 * t2 + 1][0] = r[2]; bhi[2 * t2 + 1][1] = r[3];         \
                ldsm4(r, sA + 30720 + bBase + t2 * 16 * GSTRIDE + koff);      \
                blo[2 * t2][0] = r[0]; blo[2 * t2][1] = r[1];                 \
                blo[2 * t2 + 1][0] = r[2]; blo[2 * t2 + 1][1] = r[3];         \
            }                                                                 \
            _Pragma("unroll")                                                 \
            for (int mf = 0; mf < 2; mf++)                                    \
                _Pragma("unroll")                                             \
                for (int nf = 0; nf < 8; nf++) {                              \
                    mma_bf16(acc[mf][nf], ahi[mf], bhi[nf]);                  \
                    mma_bf16(acc[mf][nf], ahi[mf], blo[nf]);                  \
                    mma_bf16(acc[mf][nf], alo[mf], bhi[nf]);                  \
                }                                                             \
        }                                                                     \
        __syncthreads();                                                      \
    }

// ---------------------------------------------------------------------------
// GEMM with fp32 output (used for the output projection)
// ---------------------------------------------------------------------------
__global__ __launch_bounds__(256, 1) void gemm_bf16s_kernel(
    const float* __restrict__ A, const float* __restrict__ Bt,
    const float* __restrict__ bias, float* __restrict__ C,
    int M, int N, int K)
{
    GEMM_CORE_BODY
    const int erow = m0 + wm * 32 + (lid >> 2);
    const int ecol0 = n0 + wn * 64 + (lid & 3) * 2;
#pragma unroll
    for (int mf = 0; mf < 2; mf++) {
#pragma unroll
        for (int nf = 0; nf < 8; nf++) {
            int col = ecol0 + nf * 8;
            float2 bz = *(const float2*)(bias + col);
            float2 v0, v1;
            v0.x = acc[mf][nf][0] + bz.x; v0.y = acc[mf][nf][1] + bz.y;
            v1.x = acc[mf][nf][2] + bz.x; v1.y = acc[mf][nf][3] + bz.y;
            size_t r0 = (size_t)(erow + mf * 16) * N + col;
            *(float2*)(C + r0) = v0;
            *(float2*)(C + r0 + 8 * N) = v1;
        }
    }
}

// ---------------------------------------------------------------------------
// QKV GEMM: writes bf16 hi/lo planes (Q pre-scaled) instead of fp32
// ---------------------------------------------------------------------------
__global__ __launch_bounds__(256, 1) void gemm_qkv_kernel(
    const float* __restrict__ A, const float* __restrict__ Bt,
    const float* __restrict__ bias,
    __nv_bfloat16* __restrict__ qhi, __nv_bfloat16* __restrict__ qlo,
    __nv_bfloat16* __restrict__ khi, __nv_bfloat16* __restrict__ klo,
    __nv_bfloat16* __restrict__ vhi, __nv_bfloat16* __restrict__ vlo,
    int M, int N, int K)
{
    GEMM_CORE_BODY
    const int t = n0 >> 11;                 // 0=Q 1=K 2=V
    const int head = (n0 >> 7) & (HEADS - 1);
    __nv_bfloat16 *phi, *plo;
    if (t == 0)      { phi = qhi; plo = qlo; }
    else if (t == 1) { phi = khi; plo = klo; }
    else             { phi = vhi; plo = vlo; }
    const float sc = (t == 0) ? 0.08838834764831845f : 1.0f;
    const int erow = m0 + wm * 32 + (lid >> 2);
    const int lcol0 = wn * 64 + (lid & 3) * 2;
#pragma unroll
    for (int mf = 0; mf < 2; mf++) {
        int tok0 = erow + mf * 16;
        int b = tok0 >> 11;
        int s0 = tok0 & 2047;
        size_t pb = ((size_t)(b * HEADS + head) * S_LEN) * HD;
#pragma unroll
        for (int nf = 0; nf < 8; nf++) {
            int lc = lcol0 + nf * 8;
            float2 bz = *(const float2*)(bias + n0 + lc);
            float v0 = (acc[mf][nf][0] + bz.x) * sc;
            float v1 = (acc[mf][nf][1] + bz.y) * sc;
            float v2 = (acc[mf][nf][2] + bz.x) * sc;
            float v3 = (acc[mf][nf][3] + bz.y) * sc;
            uint32_t h, l;
            split_bf16x2(v0, v1, h, l);
            size_t p0 = pb + (size_t)s0 * HD + lc;
            *(uint32_t*)(phi + p0) = h;
            *(uint32_t*)(plo + p0) = l;
            split_bf16x2(v2, v3, h, l);
            size_t p1 = pb + (size_t)(s0 + 8) * HD + lc;
            *(uint32_t*)(phi + p1) = h;
            *(uint32_t*)(plo + p1) = l;
        }
    }
}

// ---------------------------------------------------------------------------
// Tensor-core flash attention (bf16 3-pass split) with segment+causal mask.
// grid (32, HEADS, BATCH), 256 threads = 8 warps (4 m-slabs x 2 key-slabs).
// Q tile 64 rows, K tile 64 keys, cp.async double-buffered K/V.
// ---------------------------------------------------------------------------
#define AQ_STRIDE 272                 // smem bytes per row (136 halves)
#define APLANE    17408               // 64 * 272
#define SQHI 0
#define SQLO 17408
#define SSTAGE0 34816
#define SSTAGE_BYTES 69632            // Khi,Klo,Vhi,Vlo
#define SKHI 0
#define SKLO 17408
#define SVHI 34816
#define SVLO 52224
#define SKID  174080                  // + stage*256
#define SPMAX 174592
#define SLSUM 175104
#define ATTN_SMEM 175616

__global__ __launch_bounds__(256, 1) void attn_mma_kernel(
    const int* __restrict__ ids, float* __restrict__ out,
    const __nv_bfloat16* __restrict__ qhi, const __nv_bfloat16* __restrict__ qlo,
    const __nv_bfloat16* __restrict__ khi, const __nv_bfloat16* __restrict__ klo,
    const __nv_bfloat16* __restrict__ vhi, const __nv_bfloat16* __restrict__ vlo)
{
    extern __shared__ __align__(1024) char smem[];
    const uint32_t sb = smem_to_u32(smem);
    const int tid = threadIdx.x;
    const int lane = tid & 31, wid = tid >> 5;
    const int wm = wid >> 1, wn = wid & 1;
    const int b = blockIdx.z, h = blockIdx.y;
    const int qt = gridDim.x - 1 - blockIdx.x;       // big tiles first
    const int q0 = qt * 64;
    const size_t pbase = (size_t)(b * HEADS + h) * S_LEN * HD;
    const int* bids = ids + b * S_LEN;

    const int lr = lane >> 2;
    const int row0 = wm * 16 + lr, row1 = row0 + 8;
    const int qrow0 = q0 + row0, qrow1 = q0 + row1;
    const int qidv0 = bids[qrow0], qidv1 = bids[qrow1];
    const int qid_min = bids[q0];

    float* pmax = (float*)(smem + SPMAX);
    float* lsum = (float*)(smem + SLSUM);

    auto issue_tile = [&](int kb, int s) {
        const int k0 = kb * 64;
        const uint32_t stg = sb + SSTAGE0 + s * SSTAGE_BYTES;
#pragma unroll
        for (int j = 0; j < 4; j++) {
            int q = tid + 256 * j;
            int key = q >> 4, c16 = q & 15;
            uint32_t soff = (uint32_t)(key * AQ_STRIDE + c16 * 16);
            size_t goff = pbase + (size_t)(k0 + key) * HD + c16 * 8;
            CP_ASYNC16(stg + SKHI + soff, (const char*)(khi + goff));
            CP_ASYNC16(stg + SKLO + soff, (const char*)(klo + goff));
            CP_ASYNC16(stg + SVHI + soff, (const char*)(vhi + goff));
            CP_ASYNC16(stg + SVLO + soff, (const char*)(vlo + goff));
        }
        if (tid < 16)
            CP_ASYNC16(sb + SKID + s * 256 + tid * 16,
                       (const char*)(bids + k0 + tid * 4));
    };

    // ---- prologue: Q planes + tile 0 in cp.async group 0 ----
#pragma unroll
    for (int j = 0; j < 4; j++) {
        int q = tid + 256 * j;
        int key = q >> 4, c16 = q & 15;
        uint32_t soff = (uint32_t)(key * AQ_STRIDE + c16 * 16);
        size_t goff = pbase + (size_t)(q0 + key) * HD + c16 * 8;
        CP_ASYNC16(sb + SQHI + soff, (const char*)(qhi + goff));
        CP_ASYNC16(sb + SQLO + soff, (const char*)(qlo + goff));
    }
    issue_tile(0, 0);   // tile 0 never fully masked before the q segment? it may be,
                        // but loading it unconditionally is harmless.
    CP_COMMIT();

    float O[16][4];
#pragma unroll
    for (int nb = 0; nb < 16; nb++)
#pragma unroll
        for (int q = 0; q < 4; q++) O[nb][q] = 0.f;
    float m0r = -1e30f, m1r = -1e30f, l0r = 0.f, l1r = 0.f;

    const uint32_t qoffA = (uint32_t)((wm * 16 + (lane & 15)) * AQ_STRIDE + (lane >> 4) * 16);
    const uint32_t kBoff = (uint32_t)((wn * 32 + ((lane >> 1) & 8) + (lane & 7)) * AQ_STRIDE
                                      + ((lane & 8) << 1));
    const uint32_t vBoff = (uint32_t)((wn * 32 + ((lane >> 3) & 1) * 8 + (lane & 7)) * AQ_STRIDE
                                      + ((lane >> 4) & 1) * 16);

    const int nkb = qt;
    for (int kb = 0; kb <= nkb; kb++) {
        const int s = kb & 1;
        if (kb + 1 <= nkb) {
            bool skip_next = (bids[(kb + 1) * 64 + 63] < qid_min);
            if (!skip_next) issue_tile(kb + 1, s ^ 1);
        }
        CP_COMMIT();
        CP_WAIT1();
        __syncthreads();

        bool skip_cur = (bids[kb * 64 + 63] < qid_min);
        if (!skip_cur) {
            const uint32_t stg = sb + SSTAGE0 + s * SSTAGE_BYTES;
            const int k0 = kb * 64;

            // ---- S = Q K^T (3-pass split) ----
            float S[4][4];
#pragma unroll
            for (int nf = 0; nf < 4; nf++)
#pragma unroll
                for (int c = 0; c < 4; c++) S[nf][c] = 0.f;
#pragma unroll
            for (int ks = 0; ks < 8; ks++) {
                uint32_t ah[4], al[4];
                ldsm4(ah, sb + SQHI + qoffA + ks * 32);
                ldsm4(al, sb + SQLO + qoffA + ks * 32);
                uint32_t bh0[4], bh1[4], bl0[4], bl1[4];
                ldsm4(bh0, stg + SKHI + kBoff + ks * 32);
                ldsm4(bh1, stg + SKHI + kBoff + 16 * AQ_STRIDE + ks * 32);
                ldsm4(bl0, stg + SKLO + kBoff + ks * 32);
                ldsm4(bl1, stg + SKLO + kBoff + 16 * AQ_STRIDE + ks * 32);
                mma_bf16(S[0], ah, bh0 + 0); mma_bf16(S[0], ah, bl0 + 0); mma_bf16(S[0], al, bh0 + 0);
                mma_bf16(S[1], ah, bh0 + 2); mma_bf16(S[1], ah, bl0 + 2); mma_bf16(S[1], al, bh0 + 2);
                mma_bf16(S[2], ah, bh1 + 0); mma_bf16(S[2], ah, bl1 + 0); mma_bf16(S[2], al, bh1 + 0);
                mma_bf16(S[3], ah, bh1 + 2); mma_bf16(S[3], ah, bl1 + 2); mma_bf16(S[3], al, bh1 + 2);
            }

            // ---- mask + tile row max ----
            const uint32_t kidb = sb + SKID + s * 256;
            float mt0 = -1e30f, mt1 = -1e30f;
#pragma unroll
            for (int nf = 0; nf < 4; nf++) {
                int lc = wn * 32 + nf * 8 + 2 * (lane & 3);
                int kv0, kv1;
                asm volatile("ld.shared.v2.u32 {%0,%1}, [%2];"
                             : "=r"(kv0), "=r"(kv1) : "r"(kidb + lc * 4));
                int key = k0 + lc;
                if (key     > qrow0 || kv0 != qidv0) S[nf][0] = -1e30f;
                if (key + 1 > qrow0 || kv1 != qidv0) S[nf][1] = -1e30f;
                if (key     > qrow1 || kv0 != qidv1) S[nf][2] = -1e30f;
                if (key + 1 > qrow1 || kv1 != qidv1) S[nf][3] = -1e30f;
                mt0 = fmaxf(mt0, fmaxf(S[nf][0], S[nf][1]));
                mt1 = fmaxf(mt1, fmaxf(S[nf][2], S[nf][3]));
            }
            mt0 = fmaxf(mt0, __shfl_xor_sync(0xffffffffu, mt0, 1));
            mt0 = fmaxf(mt0, __shfl_xor_sync(0xffffffffu, mt0, 2));
            mt1 = fmaxf(mt1, __shfl_xor_sync(0xffffffffu, mt1, 1));
            mt1 = fmaxf(mt1, __shfl_xor_sync(0xffffffffu, mt1, 2));
            if ((lane & 3) == 0) {
                pmax[wn * 64 + row0] = mt0;
                pmax[wn * 64 + row1] = mt1;
            }
            __syncthreads();

            float mn0 = fmaxf(m0r, fmaxf(pmax[row0], pmax[64 + row0]));
            float mn1 = fmaxf(m1r, fmaxf(pmax[row1], pmax[64 + row1]));
            float f0 = __expf(m0r - mn0), f1 = __expf(m1r - mn1);
            m0r = mn0; m1r = mn1;

            float rs0 = 0.f, rs1 = 0.f;
#pragma unroll
            for (int nf = 0; nf < 4; nf++) {
                float p0 = (S[nf][0] < -1e29f) ? 0.f : __expf(S[nf][0] - mn0);
                float p1 = (S[nf][1] < -1e29f) ? 0.f : __expf(S[nf][1] - mn0);
                float p2 = (S[nf][2] < -1e29f) ? 0.f : __expf(S[nf][2] - mn1);
                float p3 = (S[nf][3] < -1e29f) ? 0.f : __expf(S[nf][3] - mn1);
                S[nf][0] = p0; S[nf][1] = p1; S[nf][2] = p2; S[nf][3] = p3;
                rs0 += p0 + p1; rs1 += p2 + p3;
            }
            rs0 += __shfl_xor_sync(0xffffffffu, rs0, 1);
            rs0 += __shfl_xor_sync(0xffffffffu, rs0, 2);
            rs1 += __shfl_xor_sync(0xffffffffu, rs1, 1);
            rs1 += __shfl_xor_sync(0xffffffffu, rs1, 2);
            l0r = l0r * f0 + rs0;
            l1r = l1r * f1 + rs1;

            // rescale O
#pragma unroll
            for (int nb = 0; nb < 16; nb++) {
                O[nb][0] *= f0; O[nb][1] *= f0;
                O[nb][2] *= f1; O[nb][3] *= f1;
            }

            // ---- O += P V (3-pass split) ----
#pragma unroll
            for (int ks2 = 0; ks2 < 2; ks2++) {
                uint32_t ah[4], al[4];
                split_bf16x2(S[2 * ks2][0],     S[2 * ks2][1],     ah[0], al[0]);
                split_bf16x2(S[2 * ks2][2],     S[2 * ks2][3],     ah[1], al[1]);
                split_bf16x2(S[2 * ks2 + 1][0], S[2 * ks2 + 1][1], ah[2], al[2]);
                split_bf16x2(S[2 * ks2 + 1][2], S[2 * ks2 + 1][3], ah[3], al[3]);
                uint32_t ro = vBoff + ks2 * 16 * AQ_STRIDE;
#pragma unroll
                for (int nb = 0; nb < 8; nb++) {
                    uint32_t bh[4], bl[4];
                    ldsm4t(bh, stg + SVHI + ro + nb * 32);
                    ldsm4t(bl, stg + SVLO + ro + nb * 32);
                    mma_bf16(O[2 * nb],     ah, bh + 0);
                    mma_bf16(O[2 * nb],     ah, bl + 0);
                    mma_bf16(O[2 * nb],     al, bh + 0);
                    mma_bf16(O[2 * nb + 1], ah, bh + 2);
                    mma_bf16(O[2 * nb + 1], ah, bl + 2);
                    mma_bf16(O[2 * nb + 1], al, bh + 2);
                }
            }
        }
        __syncthreads();
    }

    // ---- epilogue: combine l across warp pairs, then O, then write ----
    if ((lane & 3) == 0) {
        lsum[wn * 64 + row0] = l0r;
        lsum[wn * 64 + row1] = l1r;
    }
    __syncthreads();
    float inv0 = 1.f / (lsum[row0] + lsum[64 + row0]);
    float inv1 = 1.f / (lsum[row1] + lsum[64 + row1]);

    // O exchange via Q smem area (no longer needed)
    if (wn == 1) {
#pragma unroll
        for (int nb = 0; nb < 16; nb++) {
            uint32_t off = (uint32_t)(wm * 8192 + lr * 512 + (nb * 8 + 2 * (lane & 3)) * 4);
            *(float2*)(smem + off) = make_float2(O[nb][0], O[nb][1]);
            *(float2*)(smem + off + 8 * 512) = make_float2(O[nb][2], O[nb][3]);
        }
    }
    __syncthreads();
    if (wn == 0) {
        const size_t g0 = ((size_t)b * S_LEN + qrow0) * DIM + h * HD;
        const size_t g1 = ((size_t)b * S_LEN + qrow1) * DIM + h * HD;
#pragma unroll
        for (int nb = 0; nb < 16; nb++) {
            int col = nb * 8 + 2 * (lane & 3);
            uint32_t off = (uint32_t)(wm * 8192 + lr * 512 + col * 4);
            float2 o0 = *(float2*)(smem + off);
            float2 o1 = *(float2*)(smem + off + 8 * 512);
            float2 w0 = make_float2((O[nb][0] + o0.x) * inv0, (O[nb][1] + o0.y) * inv0);
            float2 w1 = make_float2((O[nb][2] + o1.x) * inv1, (O[nb][3] + o1.y) * inv1);
            *(float2*)(out + g0 + col) = w0;
            *(float2*)(out + g1 + col) = w1;
        }
    }
}

// ---------------------------------------------------------------------------
extern "C" void kernel_launch(void* const* d_in, const int* in_sizes, int n_in,
                              void* d_out, int out_size)
{
    const float* x    = (const float*)d_in[0];   // [4,2048,2048]
    const int*   ids  = (const int*)d_in[1];     // [4,2048]
    const float* Wqkv = (const float*)d_in[2];   // [2048,6144]
    const float* bqkv = (const float*)d_in[3];   // [6144]
    const float* Wo   = (const float*)d_in[4];   // [2048,2048]
    const float* bo   = (const float*)d_in[5];   // [2048]
    float* out = (float*)d_out;

    float *attn_ptr, *wqkvT_ptr, *woT_ptr;
    __nv_bfloat16 *qhi, *qlo, *khi, *klo, *vhi, *vlo;
    cudaGetSymbolAddress((void**)&attn_ptr, g_attn);
    cudaGetSymbolAddress((void**)&wqkvT_ptr, g_wqkvT);
    cudaGetSymbolAddress((void**)&woT_ptr, g_woT);
    cudaGetSymbolAddress((void**)&qhi, g_qhi);
    cudaGetSymbolAddress((void**)&qlo, g_qlo);
    cudaGetSymbolAddress((void**)&khi, g_khi);
    cudaGetSymbolAddress((void**)&klo, g_klo);
    cudaGetSymbolAddress((void**)&vhi, g_vhi);
    cudaGetSymbolAddress((void**)&vlo, g_vlo);

    cudaFuncSetAttribute(gemm_bf16s_kernel,
                         cudaFuncAttributeMaxDynamicSharedMemorySize, GSMEM_BYTES);
    cudaFuncSetAttribute(gemm_qkv_kernel,
                         cudaFuncAttributeMaxDynamicSharedMemorySize, GSMEM_BYTES);
    cudaFuncSetAttribute(attn_mma_kernel,
                         cudaFuncAttributeMaxDynamicSharedMemorySize, ATTN_SMEM);

    const int M = BATCH * S_LEN;   // 8192

    // 0) transpose weights into K-major scratch
    {
        dim3 blk(32, 8);
        transpose_kernel<<<dim3(3 * DIM / 32, DIM / 32), blk>>>(Wqkv, wqkvT_ptr, DIM, 3 * DIM);
        transpose_kernel<<<dim3(DIM / 32, DIM / 32), blk>>>(Wo, woT_ptr, DIM, DIM);
    }
    // 1) QKV = x @ Wqkv + bqkv -> bf16 hi/lo planes (Q pre-scaled)
    {
        dim3 grid(3 * DIM / 128, M / 128);
        gemm_qkv_kernel<<<grid, 256, GSMEM_BYTES>>>(
            x, wqkvT_ptr, bqkv, qhi, qlo, khi, klo, vhi, vlo, M, 3 * DIM, DIM);
    }
    // 2) flash attention -> g_attn [8192, 2048] fp32
    {
        dim3 grid(S_LEN / 64, HEADS, BATCH);
        attn_mma_kernel<<<grid, 256, ATTN_SMEM>>>(
            ids, attn_ptr, qhi, qlo, khi, klo, vhi, vlo);
    }
    // 3) out = attn @ Wo + bo  [8192, 2048]
    {
        dim3 grid(DIM / 128, M / 128);
        gemm_bf16s_kernel<<<grid, 256, GSMEM_BYTES>>>(attn_ptr, woT_ptr, bo, out, M, DIM, DIM);
    }
}